// round 9
// baseline (speedup 1.0000x reference)
#include <cuda_runtime.h>
#include <cuda_bf16.h>

// CRF forward, scaled-probability domain. cp.async (LDGSTS) stage ring for
// feats/mask -> no LDG scoreboard on the recurrence path. f32x2-packed
// matvec (2 batches per warp), smem-broadcast p, delayed-apply renorm.
//
//   feats      : (512, 1024, 32) f32
//   mask       : (512, 1024)     f32  (0/1 semantics)
//   transition : (32, 32)        f32
//   out        : (1024,)         f32
//
// alpha_t[j] = feat[t,b,j] + logsumexp_i(alpha_{t-1}[i] + T[j,i])
// p = exp(alpha - M), E = exp(T):  q = E p ;  p' = q*(m*ef) + p*(1-m)
//
// Key fix vs R7: register-ring prefetch caused scoreboard ALIASING — the
// counting SB waits on the slot's newest producer, so every step ate ~DRAM
// latency. cp.async groups have precise age-based completion
// (wait_group 7 => stage for step t resident), so the chain never touches
// an LDG scoreboard. Stage lead = 8 steps (~800 cyc) >> DRAM latency.
//
// Renorm: delayed-apply, period 4: snapshot s = max(p) off-chain, apply 1/s
// one period later (one MUL on-chain). 8-step unapplied growth < 2^110.
//
// 512 warps = 128 blocks x 128 threads -> 1 warp/SMSP on 128 SMs.

#define SEQ   512
#define BATCH 1024
#define TAGS  32
#define START_TAG 30
#define END_TAG   31
#define WPB   4
#define TPB   128
#define NBLOCKS 128
#define STAGES 8

typedef unsigned long long u64;

__device__ __forceinline__ u64 pack2(float lo, float hi) {
    u64 r; asm("mov.b64 %0, {%1, %2};" : "=l"(r) : "f"(lo), "f"(hi)); return r;
}
__device__ __forceinline__ u64 fma2(u64 a, u64 b, u64 c) {
    u64 r; asm("fma.rn.f32x2 %0, %1, %2, %3;" : "=l"(r) : "l"(a), "l"(b), "l"(c)); return r;
}
__device__ __forceinline__ u64 add2(u64 a, u64 b) {
    u64 r; asm("add.rn.f32x2 %0, %1, %2;" : "=l"(r) : "l"(a), "l"(b)); return r;
}
__device__ __forceinline__ void unpack2(u64 v, float& lo, float& hi) {
    asm("mov.b64 {%0, %1}, %2;" : "=f"(lo), "=f"(hi) : "l"(v));
}
__device__ __forceinline__ void cpa4(unsigned dst, const float* src) {
    asm volatile("cp.async.ca.shared.global [%0], [%1], 4;" :: "r"(dst), "l"(src));
}
__device__ __forceinline__ void cpa8(unsigned dst, const float2* src) {
    asm volatile("cp.async.ca.shared.global [%0], [%1], 8;" :: "r"(dst), "l"(src));
}
__device__ __forceinline__ void cp_commit() {
    asm volatile("cp.async.commit_group;" ::: "memory");
}
template <int N>
__device__ __forceinline__ void cp_wait() {
    asm volatile("cp.async.wait_group %0;" :: "n"(N) : "memory");
}

struct WarpStage {            // one warp's staging area
    float  fA[STAGES][TAGS];  // feat batch A, lane-private
    float  fB[STAGES][TAGS];  // feat batch B, lane-private
    float2 mk[STAGES][TAGS];  // mask pair replicated per lane (no syncwarp)
};

__global__ __launch_bounds__(TPB, 1)
void crf_fwd_kernel(const float* __restrict__ feats,
                    const float* __restrict__ mask,
                    const float* __restrict__ trans,
                    float* __restrict__ out)
{
    const int j  = threadIdx.x & 31;        // tag / lane
    const int w  = threadIdx.x >> 5;        // warp in block
    const int g  = blockIdx.x * WPB + w;    // global warp id
    const int b0 = 2 * g;                   // batches b0 (lo), b0+1 (hi)

    __shared__ __align__(16) u64       sp[WPB][TAGS];  // packed p broadcast
    __shared__ __align__(16) WarpStage st[WPB];

    // smem 32-bit addresses for cp.async destinations (this lane's slots)
    const unsigned aFA = (unsigned)__cvta_generic_to_shared(&st[w].fA[0][j]);
    const unsigned aFB = (unsigned)__cvta_generic_to_shared(&st[w].fB[0][j]);
    const unsigned aMK = (unsigned)__cvta_generic_to_shared(&st[w].mk[0][j]);

    // ---- E row j, duplicated into both halves ----------------------------
    u64 e2[TAGS];
#pragma unroll
    for (int i = 0; i < TAGS; ++i) {
        const float e = __expf(trans[j * TAGS + i]);
        e2[i] = pack2(e, e);
    }
    const float eEnd = __expf(trans[END_TAG * TAGS + j]);

    // ---- init ------------------------------------------------------------
    const float pinit = (j == START_TAG) ? 1.0f : 0.0f;
    float px = pinit, py = pinit;
    float M0 = 0.0f, M1 = 0.0f;
    float invx = 1.0f, invy = 1.0f;         // pending delayed scales
    sp[w][j] = pack2(px, py);

    // ---- prologue: stage steps 0..7 (one group per step) -----------------
    const int fbA = b0 * TAGS + j;
    const int fbB = fbA + TAGS;
    const float2* __restrict__ MK2 = reinterpret_cast<const float2*>(mask);
#pragma unroll
    for (int s = 0; s < STAGES; ++s) {
        cpa4(aFA + s * (TAGS * 4), feats + s * (BATCH * TAGS) + fbA);
        cpa4(aFB + s * (TAGS * 4), feats + s * (BATCH * TAGS) + fbB);
        cpa8(aMK + s * (TAGS * 8), MK2 + s * (BATCH / 2) + g);
        cp_commit();
    }
    __syncwarp();                            // sp init visible

    // ---- main recurrence -------------------------------------------------
    for (int blk = 0; blk < SEQ / STAGES; ++blk) {
        const int t0 = blk * STAGES;

#pragma unroll
        for (int u = 0; u < STAGES; ++u) {
            // groups committed so far: 8 + (t0+u). wait<7> => completed
            // >= t0+u+1 groups => stage for step t0+u is resident.
            cp_wait<7>();

            // lane-private staged reads (LDS, 29 cyc, off the p-chain)
            const float  fa = st[w].fA[u][j];
            const float  fb = st[w].fB[u][j];
            const float2 mv = st[w].mk[u][j];

            asm volatile("" ::: "memory");

            // refill this stage with step t+8 (wraps harmlessly at the end)
            {
                const int tp = (t0 + STAGES + u) & (SEQ - 1);
                cpa4(aFA + u * (TAGS * 4), feats + tp * (BATCH * TAGS) + fbA);
                cpa4(aFB + u * (TAGS * 4), feats + tp * (BATCH * TAGS) + fbB);
                cpa8(aMK + u * (TAGS * 8), MK2 + tp * (BATCH / 2) + g);
                cp_commit();
            }

            // q2[j] = sum_i e2[i]*p2[i] : 16 broadcast LDS.128, 8 accums
            const ulonglong2* __restrict__ src =
                reinterpret_cast<const ulonglong2*>(sp[w]);
            u64 a0 = 0, a1 = 0, a2 = 0, a3 = 0, a4 = 0, a5 = 0, a6 = 0, a7 = 0;
#pragma unroll
            for (int h = 0; h < 4; ++h) {
                const ulonglong2 v0 = src[4 * h + 0];
                const ulonglong2 v1 = src[4 * h + 1];
                const ulonglong2 v2 = src[4 * h + 2];
                const ulonglong2 v3 = src[4 * h + 3];
                a0 = fma2(e2[8 * h + 0], v0.x, a0);
                a1 = fma2(e2[8 * h + 1], v0.y, a1);
                a2 = fma2(e2[8 * h + 2], v1.x, a2);
                a3 = fma2(e2[8 * h + 3], v1.y, a3);
                a4 = fma2(e2[8 * h + 4], v2.x, a4);
                a5 = fma2(e2[8 * h + 5], v2.y, a5);
                a6 = fma2(e2[8 * h + 6], v3.x, a6);
                a7 = fma2(e2[8 * h + 7], v3.y, a7);
            }
            const u64 q2 = add2(add2(add2(a0, a1), add2(a2, a3)),
                                add2(add2(a4, a5), add2(a6, a7)));
            float qx, qy; unpack2(q2, qx, qy);

            // tail: p' = q*(m*ef) + p*(1-m)   (exp latency hidden by matvec)
            const float emx = mv.x * __expf(fa);
            const float emy = mv.y * __expf(fb);
            px = fmaf(qx, emx, px * (1.0f - mv.x));
            py = fmaf(qy, emy, py * (1.0f - mv.y));

            // ---- delayed renorm, period 4 --------------------------------
            if ((u & 3) == 3) {
                px *= invx;                  // apply PREVIOUS scales
                py *= invy;
                float sx = px, sy = py;      // snapshot max (off-chain)
#pragma unroll
                for (int off = 16; off > 0; off >>= 1) {
                    sx = fmaxf(sx, __shfl_xor_sync(0xffffffffu, sx, off));
                    sy = fmaxf(sy, __shfl_xor_sync(0xffffffffu, sy, off));
                }
                M0 += __logf(sx);
                M1 += __logf(sy);
                invx = __frcp_rn(sx);
                invy = __frcp_rn(sy);
            }

            sp[w][j] = pack2(px, py);        // publish for next step
        }
    }

    // ---- epilogue --------------------------------------------------------
    px *= invx;
    py *= invy;
    float ax = px * eEnd;
    float ay = py * eEnd;
#pragma unroll
    for (int off = 16; off > 0; off >>= 1) {
        ax += __shfl_xor_sync(0xffffffffu, ax, off);
        ay += __shfl_xor_sync(0xffffffffu, ay, off);
    }
    if (j == 0) {
        out[b0]     = M0 + __logf(ax);
        out[b0 + 1] = M1 + __logf(ay);
    }
}

extern "C" void kernel_launch(void* const* d_in, const int* in_sizes, int n_in,
                              void* d_out, int out_size)
{
    const float* feats = (const float*)d_in[0];
    const float* msk   = (const float*)d_in[1];
    const float* trans = (const float*)d_in[2];
    float*       o     = (float*)d_out;

    crf_fwd_kernel<<<NBLOCKS, TPB>>>(feats, msk, trans, o);
}

// round 10
// speedup vs baseline: 1.6727x; 1.6727x over previous
#include <cuda_runtime.h>
#include <cuda_bf16.h>

// CRF forward, scaled-probability domain, f32x2-packed (2 batches/warp).
//
//   feats      : (512, 1024, 32) f32
//   mask       : (512, 1024)     f32  (0/1 semantics)
//   transition : (32, 32)        f32
//   out        : (1024,)         f32
//
// alpha_t[j] = feat[t,b,j] + logsumexp_i(alpha_{t-1}[i] + T[j,i])
// p = exp(alpha - M), E' = 2^-6 * exp(T):   q = E' p ;  p' = q*(m*ef) + p*(1-m)
//
// The constant prescale 2^-6 absorbs the mean per-step growth (~e^4), so the
// max-renorm period stretches from 4 to 16 steps (drift is a +-1.2 nat/step
// random walk; 16-step window stays far inside fp32 range). Correction is
// EXACT: each mask-applied step contributes one factor 2^-6, so
// out += cnt * 6*ln2 with cnt = sum_t mask[t,b] (one off-chain FADD/step).
//
// Renorm (period 16, delayed-apply): apply 1/s_prev at the boundary (one
// packed MUL on-chain), snapshot s = max(p) with the two chains' SHFL
// butterflies interleaved (stall amortized to ~9 cyc/step).
//
// Loads: 2 LDG/step (feats only; 8-deep register ring). Mask: 1 LDG per 16
// steps (lane-parallel chunk -> smem stage, broadcast LDS.64 per step).
// Fewer in-flight LDGs => scoreboard slot reuse distance (~3 steps) exceeds
// DRAM latency, removing the per-step long-scoreboard leak.
//
// 512 warps = 128 blocks x 128 threads -> 1 warp/SMSP on 128 SMs.

#define SEQ   512
#define BATCH 1024
#define TAGS  32
#define START_TAG 30
#define END_TAG   31
#define WPB   4
#define TPB   128
#define NBLOCKS 128
#define PERIOD 16
#define RING  8

#define CPRE        0.015625f                 // 2^-6, exact
#define LOG_CPREINV 4.1588830833596718f       // 6*ln2

typedef unsigned long long u64;

__device__ __forceinline__ u64 pack2(float lo, float hi) {
    u64 r; asm("mov.b64 %0, {%1, %2};" : "=l"(r) : "f"(lo), "f"(hi)); return r;
}
__device__ __forceinline__ void unpack2(u64 v, float& lo, float& hi) {
    asm("mov.b64 {%0, %1}, %2;" : "=f"(lo), "=f"(hi) : "l"(v));
}
__device__ __forceinline__ u64 fma2(u64 a, u64 b, u64 c) {
    u64 r; asm("fma.rn.f32x2 %0, %1, %2, %3;" : "=l"(r) : "l"(a), "l"(b), "l"(c)); return r;
}
__device__ __forceinline__ u64 add2(u64 a, u64 b) {
    u64 r; asm("add.rn.f32x2 %0, %1, %2;" : "=l"(r) : "l"(a), "l"(b)); return r;
}
__device__ __forceinline__ u64 mul2(u64 a, u64 b) {
    u64 r; asm("mul.rn.f32x2 %0, %1, %2;" : "=l"(r) : "l"(a), "l"(b)); return r;
}

__global__ __launch_bounds__(TPB, 1)
void crf_fwd_kernel(const float* __restrict__ feats,
                    const float* __restrict__ mask,
                    const float* __restrict__ trans,
                    float* __restrict__ out)
{
    const int j  = threadIdx.x & 31;        // tag / lane
    const int w  = threadIdx.x >> 5;        // warp in block
    const int g  = blockIdx.x * WPB + w;    // global warp id
    const int b0 = 2 * g;                   // batches b0 (lo half), b0+1 (hi)

    __shared__ __align__(16) u64    sp[WPB][TAGS];       // packed p broadcast
    __shared__ __align__(8)  float2 mbuf[WPB][2][PERIOD]; // mask chunk stage

    // ---- E row j, prescaled by 2^-6, duplicated into both halves ---------
    u64 e2[TAGS];
#pragma unroll
    for (int i = 0; i < TAGS; ++i) {
        const float e = __expf(trans[j * TAGS + i]) * CPRE;
        e2[i] = pack2(e, e);
    }
    const float eEnd = __expf(trans[END_TAG * TAGS + j]);

    // ---- init ------------------------------------------------------------
    const float pinit = (j == START_TAG) ? 1.0f : 0.0f;
    u64 p2 = pack2(pinit, pinit);
    float M0 = 0.0f, M1 = 0.0f;
    float cntA = 0.0f, cntB = 0.0f;           // # applied steps per batch
    u64 pinv2 = pack2(1.0f, 1.0f);            // pending delayed scale
    sp[w][j] = p2;

    // ---- feat ring (8 deep, 2 LDG/step) ----------------------------------
    const int fbA = b0 * TAGS + j;
    const int fbB = fbA + TAGS;
    float rA[RING], rB[RING];
#pragma unroll
    for (int s = 0; s < RING; ++s) {
        rA[s] = feats[s * (BATCH * TAGS) + fbA];
        rB[s] = feats[s * (BATCH * TAGS) + fbB];
    }

    // ---- mask chunk staging: chunk0 -> smem buf0, chunk1 -> reg ----------
    const float2* __restrict__ MK2 = reinterpret_cast<const float2*>(mask);
    float2 mreg = make_float2(1.0f, 1.0f);
    if (j < PERIOD) {
        mbuf[w][0][j] = MK2[j * (BATCH / 2) + g];
        mreg          = MK2[(PERIOD + j) * (BATCH / 2) + g];
    }
    __syncwarp();                             // sp + mbuf visible

    // ---- prepare step 0 (em/om one step ahead of use) --------------------
    float2 mnext = mbuf[w][0][0];
    u64 em2 = pack2(mnext.x * __expf(rA[0]), mnext.y * __expf(rB[0]));
    u64 om2 = pack2(1.0f - mnext.x, 1.0f - mnext.y);

    // ---- main recurrence: 32 blocks x 16 unrolled steps ------------------
    for (int blk = 0; blk < SEQ / PERIOD; ++blk) {
        const int t0 = blk * PERIOD;

#pragma unroll
        for (int u = 0; u < PERIOD; ++u) {
            const u64    emc = em2, omc = om2;
            const float2 mc  = mnext;

            // ---- mask chunk management, once per block (at u==0) ---------
            if (u == 0 && j < PERIOD) {
                mbuf[w][(blk + 1) & 1][j] = mreg;            // stage blk+1
                const int cn = ((blk + 2) & 31) * PERIOD;    // load blk+2
                mreg = MK2[(cn + j) * (BATCH / 2) + g];
            }

            // ---- prepare em/om for step t+1 ------------------------------
            {
                const int slot = (u + 1) & (RING - 1);
                const float2 mn = (u == 15)
                    ? mbuf[w][(blk + 1) & 1][0]
                    : mbuf[w][blk & 1][(u + 1) & (PERIOD - 1)];
                em2 = pack2(mn.x * __expf(rA[slot]),
                            mn.y * __expf(rB[slot]));
                om2 = pack2(1.0f - mn.x, 1.0f - mn.y);
                mnext = mn;
            }

            // ---- refill ring slot (u&7) with step t+8 --------------------
            {
                const int tp = (t0 + u + RING) & (SEQ - 1);
                rA[u & (RING - 1)] = feats[tp * (BATCH * TAGS) + fbA];
                rB[u & (RING - 1)] = feats[tp * (BATCH * TAGS) + fbB];
            }

            asm volatile("" ::: "memory");    // keep prior STS before LDS

            // ---- q2[j] = sum_i e2[i]*P[i]: 16 LDS.128, 4 accums ----------
            const ulonglong2* __restrict__ src =
                reinterpret_cast<const ulonglong2*>(sp[w]);
            u64 a0 = 0, a1 = 0, a2 = 0, a3 = 0;
#pragma unroll
            for (int h = 0; h < 4; ++h) {
                const ulonglong2 v0 = src[4 * h + 0];
                const ulonglong2 v1 = src[4 * h + 1];
                const ulonglong2 v2 = src[4 * h + 2];
                const ulonglong2 v3 = src[4 * h + 3];
                a0 = fma2(e2[8 * h + 0], v0.x, a0);
                a1 = fma2(e2[8 * h + 1], v0.y, a1);
                a2 = fma2(e2[8 * h + 2], v1.x, a2);
                a3 = fma2(e2[8 * h + 3], v1.y, a3);
                a0 = fma2(e2[8 * h + 4], v2.x, a0);
                a1 = fma2(e2[8 * h + 5], v2.y, a1);
                a2 = fma2(e2[8 * h + 6], v3.x, a2);
                a3 = fma2(e2[8 * h + 7], v3.y, a3);
            }
            const u64 q2 = add2(add2(a0, a1), add2(a2, a3));

            // ---- fully-packed tail: p' = q*em + p*om ---------------------
            p2 = fma2(q2, emc, mul2(p2, omc));

            // ---- applied-step counters (off-chain) -----------------------
            cntA += mc.x;
            cntB += mc.y;

            // ---- delayed renorm, period 16 -------------------------------
            if (u == PERIOD - 1) {
                p2 = mul2(p2, pinv2);          // apply PREVIOUS scale
                float sx, sy; unpack2(p2, sx, sy);
                // interleaved butterflies (independent chains)
#pragma unroll
                for (int off = 16; off > 0; off >>= 1) {
                    const float tx = __shfl_xor_sync(0xffffffffu, sx, off);
                    const float ty = __shfl_xor_sync(0xffffffffu, sy, off);
                    sx = fmaxf(sx, tx);
                    sy = fmaxf(sy, ty);
                }
                M0 += __logf(sx);
                M1 += __logf(sy);
                pinv2 = pack2(__frcp_rn(sx), __frcp_rn(sy));
            }

            sp[w][j] = p2;                     // publish for next step
        }
    }

    // ---- epilogue --------------------------------------------------------
    p2 = mul2(p2, pinv2);                      // apply final pending scale
    float px, py; unpack2(p2, px, py);
    float ax = px * eEnd;
    float ay = py * eEnd;
#pragma unroll
    for (int off = 16; off > 0; off >>= 1) {
        ax += __shfl_xor_sync(0xffffffffu, ax, off);
        ay += __shfl_xor_sync(0xffffffffu, ay, off);
    }
    if (j == 0) {
        out[b0]     = M0 + __logf(ax) + cntA * LOG_CPREINV;
        out[b0 + 1] = M1 + __logf(ay) + cntB * LOG_CPREINV;
    }
}

extern "C" void kernel_launch(void* const* d_in, const int* in_sizes, int n_in,
                              void* d_out, int out_size)
{
    const float* feats = (const float*)d_in[0];
    const float* msk   = (const float*)d_in[1];
    const float* trans = (const float*)d_in[2];
    float*       o     = (float*)d_out;

    crf_fwd_kernel<<<NBLOCKS, TPB>>>(feats, msk, trans, o);
}